// round 13
// baseline (speedup 1.0000x reference)
#include <cuda_runtime.h>

#define BATCH   1024
#define TSTEPS  100
#define L0      30
#define C1      16
#define L1      24
#define K1      7
#define C2      32
#define L2      20
#define K2      5
#define C3      64
#define L3      18
#define K3      3
#define F1      1152   // 64*18
#define H1      256
#define NC      10

#define NTHREADS 128
#define S1ROW 52     // padded word stride per ci-pair, s1
#define S2ROW 44     // padded word stride per ci-pair, s2

typedef unsigned long long u64;
typedef unsigned short u16;

// Transposed fc1 weights: fw1T[i*H1 + j] = fw1[j*F1 + i]
__device__ __align__(16) float g_fw1T[F1 * H1];
// Prepacked conv weights (interleaved ci-pairs), shared across CTAs via L1
__device__ __align__(16) float g_w2p[C1 * K2 * C2];   // [((ci/2)*K2+k)*C2+co]*2+e
__device__ __align__(16) float g_w3p[C2 * K3 * C3];   // [((ci/2)*K3+k)*C3+co]*2+e

__global__ void transpose_fw1_kernel(const float* __restrict__ fw1) {
    int idx = blockIdx.x * blockDim.x + threadIdx.x;
    if (idx < H1 * F1) {
        int j = idx / F1;
        int i = idx - j * F1;
        g_fw1T[i * H1 + j] = fw1[idx];
    }
}

__global__ void pack_weights_kernel(const float* __restrict__ w2,
                                    const float* __restrict__ w3) {
    int idx = blockIdx.x * blockDim.x + threadIdx.x;
    if (idx < C2 * C1 * K2) {
        int co = idx / (C1 * K2);
        int r = idx - co * (C1 * K2);
        int ci = r / K2, k = r - ci * K2;
        g_w2p[(((ci >> 1) * K2 + k) * C2 + co) * 2 + (ci & 1)] = w2[idx];
    }
    if (idx < C3 * C2 * K3) {
        int co = idx / (C2 * K3);
        int r = idx - co * (C2 * K3);
        int ci = r / K3, k = r - ci * K3;
        g_w3p[(((ci >> 1) * K3 + k) * C3 + co) * 2 + (ci & 1)] = w3[idx];
    }
}

// ---- f32x2 helpers ----
__device__ __forceinline__ u64 ffma2(u64 a, u64 b, u64 c) {
    u64 d; asm("fma.rn.f32x2 %0, %1, %2, %3;" : "=l"(d) : "l"(a), "l"(b), "l"(c)); return d;
}
__device__ __forceinline__ u64 fadd2(u64 a, u64 b) {
    u64 d; asm("add.rn.f32x2 %0, %1, %2;" : "=l"(d) : "l"(a), "l"(b)); return d;
}
__device__ __forceinline__ u64 pack2(float lo, float hi) {
    u64 r; asm("mov.b64 %0, {%1, %2};" : "=l"(r) : "f"(lo), "f"(hi)); return r;
}
__device__ __forceinline__ void unpack2(u64 v, float& lo, float& hi) {
    asm("mov.b64 {%0, %1}, %2;" : "=f"(lo), "=f"(hi) : "l"(v));
}
// L2-only loads (keep L1 for the hot weight set)
__device__ __forceinline__ u64 ldcg64(const void* p) {
    u64 d; asm volatile("ld.global.cg.b64 %0, [%1];" : "=l"(d) : "l"(p)); return d;
}
__device__ __forceinline__ ulonglong2 ldcg128(const void* p) {
    ulonglong2 d;
    asm volatile("ld.global.cg.v2.u64 {%0, %1}, [%2];" : "=l"(d.x), "=l"(d.y) : "l"(p));
    return d;
}

// LIF: reset from PREVIOUS mem (subtract), spike on new mem.
__device__ __forceinline__ float lif_new_mem(float m_old, float h) {
    float reset = (m_old > 1.0f) ? 1.0f : 0.0f;
    return __fadd_rn(__fadd_rn(__fmul_rn(0.9f, m_old), h), -reset);
}

// Dense conv on f32x2 ci-pairs; spike window via even-aligned LDS.128 pairs;
// warp-uniform weight loads via __ldg (1-sector L1 hits shared across CTAs).
template<int LEN, int K, int NP, int COUT, int SROW, int PARITY>
__device__ __forceinline__ void conv_pair(const float* __restrict__ gwp,
                                          const float* __restrict__ sbase,
                                          int co, u64 binit, u64* acc) {
    constexpr int NPAIR = (LEN + K + PARITY) / 2;
    #pragma unroll
    for (int q = 0; q < LEN; q++) acc[q] = binit;
    #pragma unroll 4
    for (int p = 0; p < NP; p++) {
        u64 w[K];
        #pragma unroll
        for (int k = 0; k < K; k++)
            w[k] = __ldg((const u64*)(gwp + ((p * K + k) * COUT + co) * 2));
        const ulonglong2* sp = (const ulonglong2*)(sbase + p * SROW);
        #pragma unroll
        for (int dp = 0; dp < NPAIR; dp++) {
            ulonglong2 v = sp[dp];
            #pragma unroll
            for (int k = 0; k < K; k++) {
                int q0 = 2 * dp - PARITY - k;
                if (q0 >= 0 && q0 < LEN) acc[q0] = ffma2(w[k], v.x, acc[q0]);
            }
            #pragma unroll
            for (int k = 0; k < K; k++) {
                int q1 = 2 * dp + 1 - PARITY - k;
                if (q1 >= 0 && q1 < LEN) acc[q1] = ffma2(w[k], v.y, acc[q1]);
            }
        }
    }
}

// smem layout (words), one sample per CTA
#define OFF_SW1T 0        // 112: [k*16+co]
#define OFF_SB1  112      // 16
#define OFF_XB   128      // 64: [buf*32 + l]
#define OFF_S1   192      // 416: [p*52 + l*2 + e]  (16B aligned)
#define OFF_S2   608      // 704: [p*44 + l*2 + e]  (16B aligned)
#define OFF_S4   1312     // 256: [j]
#define OFF_NACT 1568     // 4
#define OFF_ACT  1572     // 576 words = 4 segments * 288 u16 (byte 6288, 16-aligned)
#define SMEM_WORDS 2148
#define SMEM_BYTES (SMEM_WORDS * 4)

__global__ __launch_bounds__(NTHREADS, 8)
void snn_kernel(const float* __restrict__ x,
                const float* __restrict__ w1, const float* __restrict__ b1,
                const float* __restrict__ b2v, const float* __restrict__ b3v,
                const float* __restrict__ fb1,
                const float* __restrict__ fw2, const float* __restrict__ fb2,
                float* __restrict__ out)
{
    extern __shared__ float smem[];
    float* sw1t = smem + OFF_SW1T;
    float* sb1  = smem + OFF_SB1;
    float* xb    = smem + OFF_XB;
    float* s1p   = smem + OFF_S1;
    float* s2p   = smem + OFF_S2;
    float* s4buf = smem + OFF_S4;
    int* nacts = (int*)(smem + OFF_NACT);
    u16* act = (u16*)(smem + OFF_ACT);   // 4 segments of 288

    const int tid  = threadIdx.x;
    const int lane = tid & 31;
    const int warp = tid >> 5;            // 0..3
    const int b = blockIdx.x;             // one sample per CTA

    // ---- conv1 weights/biases into smem ----
    for (int i = tid; i < C1 * K1; i += NTHREADS) {
        int co = i / K1, k = i - co * K1;
        sw1t[k * C1 + co] = w1[i];
    }
    if (tid < C1) sb1[tid] = b1[tid];
    // x prefetch for t=0
    if (warp == 0 && lane < L0)
        xb[lane] = __ldg(&x[b * (L0 * TSTEPS) + lane * TSTEPS]);

    // ---- per-thread register state ----
    float m1r[3] = {0.0f, 0.0f, 0.0f};
    const float b2r = __ldg(&b2v[lane]);
    float m2r[5] = {0.0f, 0.0f, 0.0f, 0.0f, 0.0f};
    const int l02 = warp * 5;                  // conv2: {5,5,5,5}
    const int co3 = ((warp & 1) << 5) | lane;  // conv3: {9,9}
    const int T3  = warp >> 1;
    const int l03 = T3 * 9;
    const float b3r = __ldg(&b3v[co3]);
    float m3r[9];
    #pragma unroll
    for (int q = 0; q < 9; q++) m3r[q] = 0.0f;
    float m4r[4] = {0.0f, 0.0f, 0.0f, 0.0f};   // fc1: 64 threads x 4 outputs
    float m5r[3] = {0.0f, 0.0f, 0.0f};
    __syncthreads();

    for (int t = 0; t < TSTEPS; t++) {
        // ======== conv1 (1->16, k=7): 128 threads, 3 outputs each ========
        {
            const float* xr = xb + (t & 1) * 32;
            if (warp == 0 && lane < L0 && t + 1 < TSTEPS)
                xb[((t + 1) & 1) * 32 + lane] =
                    __ldg(&x[b * (L0 * TSTEPS) + lane * TSTEPS + t + 1]);
            #pragma unroll
            for (int it = 0; it < 3; it++) {
                int idx = tid + it * 128;
                int l = idx >> 4, co = idx & 15;
                float acc = sb1[co];
                #pragma unroll
                for (int k = 0; k < K1; k++)
                    acc = fmaf(sw1t[k * C1 + co], xr[l + k], acc);
                float mn = lif_new_mem(m1r[it], acc);
                m1r[it] = mn;
                s1p[(co >> 1) * S1ROW + l * 2 + (co & 1)] = (mn > 1.0f) ? 1.0f : 0.0f;
            }
        }
        __syncthreads();   // S1

        // ======== conv2 (16->32, k=5): co=lane, 5 l per thread ========
        {
            u64 acc[5];
            const float* sb = s1p + (l02 & ~1) * 2;
            if (warp & 1)
                conv_pair<5, K2, 8, C2, S1ROW, 1>(g_w2p, sb, lane, pack2(b2r, 0.0f), acc);
            else
                conv_pair<5, K2, 8, C2, S1ROW, 0>(g_w2p, sb, lane, pack2(b2r, 0.0f), acc);
            #pragma unroll
            for (int q = 0; q < 5; q++) {
                float lo, hi; unpack2(acc[q], lo, hi);
                float h = __fadd_rn(lo, hi);
                float mn = lif_new_mem(m2r[q], h);
                m2r[q] = mn;
                s2p[(lane >> 1) * S2ROW + (l02 + q) * 2 + (lane & 1)] = (mn > 1.0f) ? 1.0f : 0.0f;
            }
        }
        __syncthreads();   // S2

        // ======== conv3 (32->64, k=3) + per-warp active-list segment ========
        {
            u64 acc[9];
            if (T3 == 0)
                conv_pair<9, K3, 16, C3, S2ROW, 0>(g_w3p, s2p, co3, pack2(b3r, 0.0f), acc);
            else
                conv_pair<9, K3, 16, C3, S2ROW, 1>(g_w3p, s2p + 8 * 2, co3, pack2(b3r, 0.0f), acc);
            unsigned bits = 0;
            #pragma unroll
            for (int q = 0; q < 9; q++) {
                float lo, hi; unpack2(acc[q], lo, hi);
                float h = __fadd_rn(lo, hi);
                float mn = lif_new_mem(m3r[q], h);
                m3r[q] = mn;
                if (mn > 1.0f) bits |= 1u << q;
            }
            // warp-local segment build (no extra barrier, no mask array)
            int cnt = __popc(bits);
            int pos = cnt;
            #pragma unroll
            for (int o = 1; o < 32; o <<= 1) {
                int v = __shfl_up_sync(0xffffffff, pos, o);
                if (lane >= o) pos += v;
            }
            if (lane == 31) nacts[warp] = pos;
            u16* ap = act + warp * 288 + (pos - cnt);
            int gbase = co3 * L3 + l03;
            unsigned m = bits;
            while (m) {
                int q = __ffs(m) - 1; m &= m - 1;
                *ap++ = (u16)(gbase + q);
            }
        }
        __syncthreads();   // S3

        // ======== fc1 (1152->256): 64 threads, 4 outputs each (LDG.128) ========
        if (tid < 64) {
            ulonglong2 acc;
            acc.x = __ldg((const u64*)(fb1 + 4 * tid));
            acc.y = __ldg((const u64*)(fb1 + 4 * tid + 2));
            const char* base = (const char*)(g_fw1T + 4 * tid);
            #pragma unroll
            for (int w = 0; w < 4; w++) {
                const int na = nacts[w];
                const u16* ap = act + w * 288;
                const u64* actq = (const u64*)ap;
                int a = 0;
                for (; a + 4 <= na; a += 4) {
                    u64 four = actq[a >> 2];
                    unsigned i0 = (unsigned)(four & 0xFFFFu);
                    unsigned i1 = (unsigned)((four >> 16) & 0xFFFFu);
                    unsigned i2 = (unsigned)((four >> 32) & 0xFFFFu);
                    unsigned i3 = (unsigned)(four >> 48);
                    ulonglong2 v0 = ldcg128(base + i0 * (H1 * 4));
                    ulonglong2 v1 = ldcg128(base + i1 * (H1 * 4));
                    ulonglong2 v2 = ldcg128(base + i2 * (H1 * 4));
                    ulonglong2 v3 = ldcg128(base + i3 * (H1 * 4));
                    acc.x = fadd2(acc.x, v0.x); acc.y = fadd2(acc.y, v0.y);
                    acc.x = fadd2(acc.x, v1.x); acc.y = fadd2(acc.y, v1.y);
                    acc.x = fadd2(acc.x, v2.x); acc.y = fadd2(acc.y, v2.y);
                    acc.x = fadd2(acc.x, v3.x); acc.y = fadd2(acc.y, v3.y);
                }
                for (; a < na; a++) {
                    unsigned i0 = ap[a];
                    ulonglong2 v = ldcg128(base + i0 * (H1 * 4));
                    acc.x = fadd2(acc.x, v.x);
                    acc.y = fadd2(acc.y, v.y);
                }
            }
            float f0, f1, f2, f3;
            unpack2(acc.x, f0, f1);
            unpack2(acc.y, f2, f3);
            float mn0 = lif_new_mem(m4r[0], f0);
            float mn1 = lif_new_mem(m4r[1], f1);
            float mn2 = lif_new_mem(m4r[2], f2);
            float mn3 = lif_new_mem(m4r[3], f3);
            m4r[0] = mn0; m4r[1] = mn1; m4r[2] = mn2; m4r[3] = mn3;
            float4 sp;
            sp.x = (mn0 > 1.0f) ? 1.0f : 0.0f;
            sp.y = (mn1 > 1.0f) ? 1.0f : 0.0f;
            sp.z = (mn2 > 1.0f) ? 1.0f : 0.0f;
            sp.w = (mn3 > 1.0f) ? 1.0f : 0.0f;
            *(float4*)(s4buf + 4 * tid) = sp;
        }
        __syncthreads();   // S4

        // ======== fc2 (256->10) + output ========
        {
            #pragma unroll
            for (int i = 0; i < 3; i++) {
                int j = warp + 4 * i;
                if (j < NC) {
                    float acc = 0.0f;
                    #pragma unroll
                    for (int q = 0; q < 8; q++) {
                        int ii = lane + 32 * q;
                        acc = fmaf(__ldg(&fw2[j * H1 + ii]), s4buf[ii], acc);
                    }
                    #pragma unroll
                    for (int o = 16; o > 0; o >>= 1)
                        acc += __shfl_down_sync(0xffffffff, acc, o);
                    if (lane == 0) {
                        acc += __ldg(&fb2[j]);
                        float mn = lif_new_mem(m5r[i], acc);
                        m5r[i] = mn;
                        out[(t * BATCH + b) * NC + j] = (mn > 1.0f) ? 1.0f : 0.0f;
                    }
                }
            }
        }
        // no trailing barrier: fc2 reads only s4buf/fw2; s4's next writer (fc1)
        // is three barriers away; next conv1 writes s1p/xb whose readers are behind S1.
    }
}

extern "C" void kernel_launch(void* const* d_in, const int* in_sizes, int n_in,
                              void* d_out, int out_size) {
    const float* x   = (const float*)d_in[0];
    const float* w1  = (const float*)d_in[1];
    const float* b1  = (const float*)d_in[2];
    const float* w2  = (const float*)d_in[3];
    const float* b2  = (const float*)d_in[4];
    const float* w3  = (const float*)d_in[5];
    const float* b3  = (const float*)d_in[6];
    const float* fw1 = (const float*)d_in[7];
    const float* fb1 = (const float*)d_in[8];
    const float* fw2 = (const float*)d_in[9];
    const float* fb2 = (const float*)d_in[10];
    float* out = (float*)d_out;

    cudaFuncSetAttribute(snn_kernel, cudaFuncAttributeMaxDynamicSharedMemorySize, SMEM_BYTES);

    transpose_fw1_kernel<<<(H1 * F1 + 255) / 256, 256>>>(fw1);
    pack_weights_kernel<<<(C3 * C2 * K3 + 255) / 256, 256>>>(w2, w3);
    snn_kernel<<<BATCH, NTHREADS, SMEM_BYTES>>>(x, w1, b1, b2, b3,
                                                fb1, fw2, fb2, out);
}

// round 14
// speedup vs baseline: 1.0056x; 1.0056x over previous
#include <cuda_runtime.h>

#define BATCH   1024
#define TSTEPS  100
#define L0      30
#define C1      16
#define L1      24
#define K1      7
#define C2      32
#define L2      20
#define K2      5
#define C3      64
#define L3      18
#define K3      3
#define F1      1152   // 64*18
#define H1      256
#define NC      10

#define NTHREADS 128
#define S1ROW 52     // padded word stride per ci-pair, s1
#define S2ROW 44     // padded word stride per ci-pair, s2

typedef unsigned long long u64;
typedef unsigned short u16;

// Transposed fc1 weights: fw1T[i*H1 + j] = fw1[j*F1 + i]
__device__ __align__(16) float g_fw1T[F1 * H1];
// Prepacked conv weights (interleaved ci-pairs), shared across CTAs via L1
__device__ __align__(16) float g_w2p[C1 * K2 * C2];   // [((ci/2)*K2+k)*C2+co]*2+e
__device__ __align__(16) float g_w3p[C2 * K3 * C3];   // [((ci/2)*K3+k)*C3+co]*2+e

__global__ void transpose_fw1_kernel(const float* __restrict__ fw1) {
    int idx = blockIdx.x * blockDim.x + threadIdx.x;
    if (idx < H1 * F1) {
        int j = idx / F1;
        int i = idx - j * F1;
        g_fw1T[i * H1 + j] = fw1[idx];
    }
}

__global__ void pack_weights_kernel(const float* __restrict__ w2,
                                    const float* __restrict__ w3) {
    int idx = blockIdx.x * blockDim.x + threadIdx.x;
    if (idx < C2 * C1 * K2) {
        int co = idx / (C1 * K2);
        int r = idx - co * (C1 * K2);
        int ci = r / K2, k = r - ci * K2;
        g_w2p[(((ci >> 1) * K2 + k) * C2 + co) * 2 + (ci & 1)] = w2[idx];
    }
    if (idx < C3 * C2 * K3) {
        int co = idx / (C2 * K3);
        int r = idx - co * (C2 * K3);
        int ci = r / K3, k = r - ci * K3;
        g_w3p[(((ci >> 1) * K3 + k) * C3 + co) * 2 + (ci & 1)] = w3[idx];
    }
}

// ---- f32x2 helpers ----
__device__ __forceinline__ u64 ffma2(u64 a, u64 b, u64 c) {
    u64 d; asm("fma.rn.f32x2 %0, %1, %2, %3;" : "=l"(d) : "l"(a), "l"(b), "l"(c)); return d;
}
__device__ __forceinline__ u64 fadd2(u64 a, u64 b) {
    u64 d; asm("add.rn.f32x2 %0, %1, %2;" : "=l"(d) : "l"(a), "l"(b)); return d;
}
__device__ __forceinline__ u64 pack2(float lo, float hi) {
    u64 r; asm("mov.b64 %0, {%1, %2};" : "=l"(r) : "f"(lo), "f"(hi)); return r;
}
__device__ __forceinline__ void unpack2(u64 v, float& lo, float& hi) {
    asm("mov.b64 {%0, %1}, %2;" : "=f"(lo), "=f"(hi) : "l"(v));
}
// L2-only load (keeps L1 for the hot weight set)
__device__ __forceinline__ u64 ldcg64(const void* p) {
    u64 d; asm volatile("ld.global.cg.b64 %0, [%1];" : "=l"(d) : "l"(p)); return d;
}

// LIF: reset from PREVIOUS mem (subtract), spike on new mem.
__device__ __forceinline__ float lif_new_mem(float m_old, float h) {
    float reset = (m_old > 1.0f) ? 1.0f : 0.0f;
    return __fadd_rn(__fadd_rn(__fmul_rn(0.9f, m_old), h), -reset);
}

// Dense conv on f32x2 ci-pairs; spike window via even-aligned LDS.128 pairs;
// warp-uniform weight loads via __ldg (1-sector L1 hits shared across CTAs).
template<int LEN, int K, int NP, int COUT, int SROW, int PARITY>
__device__ __forceinline__ void conv_pair(const float* __restrict__ gwp,
                                          const float* __restrict__ sbase,
                                          int co, u64 binit, u64* acc) {
    constexpr int NPAIR = (LEN + K + PARITY) / 2;
    #pragma unroll
    for (int q = 0; q < LEN; q++) acc[q] = binit;
    #pragma unroll 4
    for (int p = 0; p < NP; p++) {
        u64 w[K];
        #pragma unroll
        for (int k = 0; k < K; k++)
            w[k] = __ldg((const u64*)(gwp + ((p * K + k) * COUT + co) * 2));
        const ulonglong2* sp = (const ulonglong2*)(sbase + p * SROW);
        #pragma unroll
        for (int dp = 0; dp < NPAIR; dp++) {
            ulonglong2 v = sp[dp];
            #pragma unroll
            for (int k = 0; k < K; k++) {
                int q0 = 2 * dp - PARITY - k;
                if (q0 >= 0 && q0 < LEN) acc[q0] = ffma2(w[k], v.x, acc[q0]);
            }
            #pragma unroll
            for (int k = 0; k < K; k++) {
                int q1 = 2 * dp + 1 - PARITY - k;
                if (q1 >= 0 && q1 < LEN) acc[q1] = ffma2(w[k], v.y, acc[q1]);
            }
        }
    }
}

// smem layout (words), one sample per CTA
#define OFF_SW1T 0        // 112: [k*16+co]
#define OFF_SB1  112      // 16
#define OFF_XB   128      // 64: [buf*32 + l]
#define OFF_S1   192      // 416: [p*52 + l*2 + e]  (16B aligned)
#define OFF_S2   608      // 704: [p*44 + l*2 + e]  (16B aligned)
#define OFF_S4   1312     // 256: [j]
#define OFF_NACT 1568     // 4
#define OFF_ACT  1572     // 576 words = 4 segments * 288 u16 (byte 6288, 16-aligned)
#define SMEM_WORDS 2148
#define SMEM_BYTES (SMEM_WORDS * 4)

__global__ __launch_bounds__(NTHREADS, 8)
void snn_kernel(const float* __restrict__ x,
                const float* __restrict__ w1, const float* __restrict__ b1,
                const float* __restrict__ b2v, const float* __restrict__ b3v,
                const float* __restrict__ fb1,
                const float* __restrict__ fw2, const float* __restrict__ fb2,
                float* __restrict__ out)
{
    extern __shared__ float smem[];
    float* sw1t = smem + OFF_SW1T;
    float* sb1  = smem + OFF_SB1;
    float* xb    = smem + OFF_XB;
    float* s1p   = smem + OFF_S1;
    float* s2p   = smem + OFF_S2;
    float* s4buf = smem + OFF_S4;
    int* nacts = (int*)(smem + OFF_NACT);
    u16* act = (u16*)(smem + OFF_ACT);   // 4 segments of 288

    const int tid  = threadIdx.x;
    const int lane = tid & 31;
    const int warp = tid >> 5;            // 0..3
    const int b = blockIdx.x;             // one sample per CTA

    // ---- conv1 weights/biases into smem ----
    for (int i = tid; i < C1 * K1; i += NTHREADS) {
        int co = i / K1, k = i - co * K1;
        sw1t[k * C1 + co] = w1[i];
    }
    if (tid < C1) sb1[tid] = b1[tid];
    // x prefetch for t=0
    if (warp == 0 && lane < L0)
        xb[lane] = __ldg(&x[b * (L0 * TSTEPS) + lane * TSTEPS]);

    // ---- per-thread register state ----
    float m1r[3] = {0.0f, 0.0f, 0.0f};
    const float b2r = __ldg(&b2v[lane]);
    float m2r[5] = {0.0f, 0.0f, 0.0f, 0.0f, 0.0f};
    const int l02 = warp * 5;                  // conv2: {5,5,5,5}
    const int co3 = ((warp & 1) << 5) | lane;  // conv3: {9,9}
    const int T3  = warp >> 1;
    const int l03 = T3 * 9;
    const float b3r = __ldg(&b3v[co3]);
    float m3r[9];
    #pragma unroll
    for (int q = 0; q < 9; q++) m3r[q] = 0.0f;
    float m4a = 0.0f, m4b = 0.0f;
    float m5r[3] = {0.0f, 0.0f, 0.0f};
    __syncthreads();

    for (int t = 0; t < TSTEPS; t++) {
        // ======== conv1 (1->16, k=7): 128 threads, 3 outputs each ========
        {
            const float* xr = xb + (t & 1) * 32;
            if (warp == 0 && lane < L0 && t + 1 < TSTEPS)
                xb[((t + 1) & 1) * 32 + lane] =
                    __ldg(&x[b * (L0 * TSTEPS) + lane * TSTEPS + t + 1]);
            #pragma unroll
            for (int it = 0; it < 3; it++) {
                int idx = tid + it * 128;
                int l = idx >> 4, co = idx & 15;
                float acc = sb1[co];
                #pragma unroll
                for (int k = 0; k < K1; k++)
                    acc = fmaf(sw1t[k * C1 + co], xr[l + k], acc);
                float mn = lif_new_mem(m1r[it], acc);
                m1r[it] = mn;
                s1p[(co >> 1) * S1ROW + l * 2 + (co & 1)] = (mn > 1.0f) ? 1.0f : 0.0f;
            }
        }
        __syncthreads();   // S1

        // ======== conv2 (16->32, k=5): co=lane, 5 l per thread ========
        {
            u64 acc[5];
            const float* sb = s1p + (l02 & ~1) * 2;
            if (warp & 1)
                conv_pair<5, K2, 8, C2, S1ROW, 1>(g_w2p, sb, lane, pack2(b2r, 0.0f), acc);
            else
                conv_pair<5, K2, 8, C2, S1ROW, 0>(g_w2p, sb, lane, pack2(b2r, 0.0f), acc);
            #pragma unroll
            for (int q = 0; q < 5; q++) {
                float lo, hi; unpack2(acc[q], lo, hi);
                float h = __fadd_rn(lo, hi);
                float mn = lif_new_mem(m2r[q], h);
                m2r[q] = mn;
                s2p[(lane >> 1) * S2ROW + (l02 + q) * 2 + (lane & 1)] = (mn > 1.0f) ? 1.0f : 0.0f;
            }
        }
        __syncthreads();   // S2

        // ======== conv3 (32->64, k=3) + per-warp active-list segment ========
        {
            u64 acc[9];
            if (T3 == 0)
                conv_pair<9, K3, 16, C3, S2ROW, 0>(g_w3p, s2p, co3, pack2(b3r, 0.0f), acc);
            else
                conv_pair<9, K3, 16, C3, S2ROW, 1>(g_w3p, s2p + 8 * 2, co3, pack2(b3r, 0.0f), acc);
            unsigned bits = 0;
            #pragma unroll
            for (int q = 0; q < 9; q++) {
                float lo, hi; unpack2(acc[q], lo, hi);
                float h = __fadd_rn(lo, hi);
                float mn = lif_new_mem(m3r[q], h);
                m3r[q] = mn;
                if (mn > 1.0f) bits |= 1u << q;
            }
            // warp-local segment build (no extra barrier, no mask array)
            int cnt = __popc(bits);
            int pos = cnt;
            #pragma unroll
            for (int o = 1; o < 32; o <<= 1) {
                int v = __shfl_up_sync(0xffffffff, pos, o);
                if (lane >= o) pos += v;
            }
            if (lane == 31) nacts[warp] = pos;
            u16* ap = act + warp * 288 + (pos - cnt);
            int gbase = co3 * L3 + l03;
            unsigned m = bits;
            while (m) {
                int q = __ffs(m) - 1; m &= m - 1;
                *ap++ = (u16)(gbase + q);
            }
        }
        __syncthreads();   // S3

        // ======== fc1 (1152->256): 128 threads, 2 outputs each ========
        {
            u64 acc = __ldg((const u64*)(fb1 + 2 * tid));
            const char* base = (const char*)(g_fw1T + 2 * tid);
            #pragma unroll
            for (int w = 0; w < 4; w++) {
                const int na = nacts[w];
                const u16* ap = act + w * 288;
                const u64* actq = (const u64*)ap;
                int a = 0;
                for (; a + 4 <= na; a += 4) {
                    u64 four = actq[a >> 2];
                    unsigned i0 = (unsigned)(four & 0xFFFFu);
                    unsigned i1 = (unsigned)((four >> 16) & 0xFFFFu);
                    unsigned i2 = (unsigned)((four >> 32) & 0xFFFFu);
                    unsigned i3 = (unsigned)(four >> 48);
                    u64 v0 = ldcg64(base + i0 * (H1 * 4));
                    u64 v1 = ldcg64(base + i1 * (H1 * 4));
                    u64 v2 = ldcg64(base + i2 * (H1 * 4));
                    u64 v3 = ldcg64(base + i3 * (H1 * 4));
                    acc = fadd2(acc, v0);
                    acc = fadd2(acc, v1);
                    acc = fadd2(acc, v2);
                    acc = fadd2(acc, v3);
                }
                for (; a < na; a++) {
                    unsigned i0 = ap[a];
                    acc = fadd2(acc, ldcg64(base + i0 * (H1 * 4)));
                }
            }
            float lo, hi; unpack2(acc, lo, hi);
            float mn0 = lif_new_mem(m4a, lo);
            float mn1 = lif_new_mem(m4b, hi);
            m4a = mn0; m4b = mn1;
            *(u64*)(s4buf + 2 * tid) =
                pack2((mn0 > 1.0f) ? 1.0f : 0.0f, (mn1 > 1.0f) ? 1.0f : 0.0f);
        }
        __syncthreads();   // S4

        // ======== fc2 (256->10) + output ========
        {
            #pragma unroll
            for (int i = 0; i < 3; i++) {
                int j = warp + 4 * i;
                if (j < NC) {
                    float acc = 0.0f;
                    #pragma unroll
                    for (int q = 0; q < 8; q++) {
                        int ii = lane + 32 * q;
                        acc = fmaf(__ldg(&fw2[j * H1 + ii]), s4buf[ii], acc);
                    }
                    #pragma unroll
                    for (int o = 16; o > 0; o >>= 1)
                        acc += __shfl_down_sync(0xffffffff, acc, o);
                    if (lane == 0) {
                        acc += __ldg(&fb2[j]);
                        float mn = lif_new_mem(m5r[i], acc);
                        m5r[i] = mn;
                        out[(t * BATCH + b) * NC + j] = (mn > 1.0f) ? 1.0f : 0.0f;
                    }
                }
            }
        }
        // no trailing barrier: fc2 reads only s4buf/fw2; s4's next writer (fc1)
        // is three barriers away; next conv1 writes s1p/xb whose readers are behind S1.
    }
}

extern "C" void kernel_launch(void* const* d_in, const int* in_sizes, int n_in,
                              void* d_out, int out_size) {
    const float* x   = (const float*)d_in[0];
    const float* w1  = (const float*)d_in[1];
    const float* b1  = (const float*)d_in[2];
    const float* w2  = (const float*)d_in[3];
    const float* b2  = (const float*)d_in[4];
    const float* w3  = (const float*)d_in[5];
    const float* b3  = (const float*)d_in[6];
    const float* fw1 = (const float*)d_in[7];
    const float* fb1 = (const float*)d_in[8];
    const float* fw2 = (const float*)d_in[9];
    const float* fb2 = (const float*)d_in[10];
    float* out = (float*)d_out;

    cudaFuncSetAttribute(snn_kernel, cudaFuncAttributeMaxDynamicSharedMemorySize, SMEM_BYTES);

    transpose_fw1_kernel<<<(H1 * F1 + 255) / 256, 256>>>(fw1);
    pack_weights_kernel<<<(C3 * C2 * K3 + 255) / 256, 256>>>(w2, w3);
    snn_kernel<<<BATCH, NTHREADS, SMEM_BYTES>>>(x, w1, b1, b2, b3,
                                                fb1, fw2, fb2, out);
}

// round 15
// speedup vs baseline: 1.0739x; 1.0679x over previous
#include <cuda_runtime.h>

#define BATCH   1024
#define TSTEPS  100
#define L0      30
#define C1      16
#define L1      24
#define K1      7
#define C2      32
#define L2      20
#define K2      5
#define C3      64
#define L3      18
#define K3      3
#define F1      1152   // 64*18
#define H1      256
#define NC      10

#define NTHREADS 128
#define S1ROW 52     // padded word stride per ci-pair, s1
#define S2ROW 44     // padded word stride per ci-pair, s2

typedef unsigned long long u64;
typedef unsigned short u16;

// Transposed fc1 weights: fw1T[i*H1 + j] = fw1[j*F1 + i]
__device__ __align__(16) float g_fw1T[F1 * H1];
// Prepacked conv weights (interleaved ci-pairs), shared across CTAs via L1
__device__ __align__(16) float g_w2p[C1 * K2 * C2];   // [((ci/2)*K2+k)*C2+co]*2+e
__device__ __align__(16) float g_w3p[C2 * K3 * C3];   // [((ci/2)*K3+k)*C3+co]*2+e

__global__ void transpose_fw1_kernel(const float* __restrict__ fw1) {
    int idx = blockIdx.x * blockDim.x + threadIdx.x;
    if (idx < H1 * F1) {
        int j = idx / F1;
        int i = idx - j * F1;
        g_fw1T[i * H1 + j] = fw1[idx];
    }
}

__global__ void pack_weights_kernel(const float* __restrict__ w2,
                                    const float* __restrict__ w3) {
    int idx = blockIdx.x * blockDim.x + threadIdx.x;
    if (idx < C2 * C1 * K2) {
        int co = idx / (C1 * K2);
        int r = idx - co * (C1 * K2);
        int ci = r / K2, k = r - ci * K2;
        g_w2p[(((ci >> 1) * K2 + k) * C2 + co) * 2 + (ci & 1)] = w2[idx];
    }
    if (idx < C3 * C2 * K3) {
        int co = idx / (C2 * K3);
        int r = idx - co * (C2 * K3);
        int ci = r / K3, k = r - ci * K3;
        g_w3p[(((ci >> 1) * K3 + k) * C3 + co) * 2 + (ci & 1)] = w3[idx];
    }
}

// ---- f32x2 helpers ----
__device__ __forceinline__ u64 ffma2(u64 a, u64 b, u64 c) {
    u64 d; asm("fma.rn.f32x2 %0, %1, %2, %3;" : "=l"(d) : "l"(a), "l"(b), "l"(c)); return d;
}
__device__ __forceinline__ u64 fadd2(u64 a, u64 b) {
    u64 d; asm("add.rn.f32x2 %0, %1, %2;" : "=l"(d) : "l"(a), "l"(b)); return d;
}
__device__ __forceinline__ u64 pack2(float lo, float hi) {
    u64 r; asm("mov.b64 %0, {%1, %2};" : "=l"(r) : "f"(lo), "f"(hi)); return r;
}
__device__ __forceinline__ void unpack2(u64 v, float& lo, float& hi) {
    asm("mov.b64 {%0, %1}, %2;" : "=f"(lo), "=f"(hi) : "l"(v));
}
// L2-only load (keeps L1 for the hot weight set)
__device__ __forceinline__ u64 ldcg64(const void* p) {
    u64 d; asm volatile("ld.global.cg.b64 %0, [%1];" : "=l"(d) : "l"(p)); return d;
}

// LIF: reset from PREVIOUS mem (subtract), spike on new mem.
__device__ __forceinline__ float lif_new_mem(float m_old, float h) {
    float reset = (m_old > 1.0f) ? 1.0f : 0.0f;
    return __fadd_rn(__fadd_rn(__fmul_rn(0.9f, m_old), h), -reset);
}

// Dense conv on f32x2 ci-pairs; spike window via even-aligned LDS.128 pairs;
// weight loads via __ldg (L1 hits shared across CTAs).
template<int LEN, int K, int NP, int COUT, int SROW, int PARITY>
__device__ __forceinline__ void conv_pair(const float* __restrict__ gwp,
                                          const float* __restrict__ sbase,
                                          int co, u64 binit, u64* acc) {
    constexpr int NPAIR = (LEN + K + PARITY) / 2;
    #pragma unroll
    for (int q = 0; q < LEN; q++) acc[q] = binit;
    #pragma unroll 4
    for (int p = 0; p < NP; p++) {
        u64 w[K];
        #pragma unroll
        for (int k = 0; k < K; k++)
            w[k] = __ldg((const u64*)(gwp + ((p * K + k) * COUT + co) * 2));
        const ulonglong2* sp = (const ulonglong2*)(sbase + p * SROW);
        #pragma unroll
        for (int dp = 0; dp < NPAIR; dp++) {
            ulonglong2 v = sp[dp];
            #pragma unroll
            for (int k = 0; k < K; k++) {
                int q0 = 2 * dp - PARITY - k;
                if (q0 >= 0 && q0 < LEN) acc[q0] = ffma2(w[k], v.x, acc[q0]);
            }
            #pragma unroll
            for (int k = 0; k < K; k++) {
                int q1 = 2 * dp + 1 - PARITY - k;
                if (q1 >= 0 && q1 < LEN) acc[q1] = ffma2(w[k], v.y, acc[q1]);
            }
        }
    }
}

// smem layout (words), one sample per CTA  (R11 layout)
#define OFF_SW1T 0        // 112: [k*16+co]
#define OFF_SB1  112      // 16
#define OFF_XB   128      // 64: [buf*32 + l]
#define OFF_S1   192      // 416: [p*52 + l*2 + e]  (16B aligned)
#define OFF_S2   608      // 704: [p*44 + l*2 + e]  (16B aligned)
#define OFF_S4   1312     // 256: [j]
#define OFF_MSK  1568     // 128: [T*64+co]
#define OFF_NACT 1696     // 2 (1 + pad for 8B-aligned act)
#define OFF_ACT  1698     // 576 words = 1152 u16 (byte 6792, 8-aligned)
#define SMEM_WORDS 2274
#define SMEM_BYTES (SMEM_WORDS * 4)

__global__ __launch_bounds__(NTHREADS, 8)
void snn_kernel(const float* __restrict__ x,
                const float* __restrict__ w1, const float* __restrict__ b1,
                const float* __restrict__ b2v, const float* __restrict__ b3v,
                const float* __restrict__ fb1,
                const float* __restrict__ fw2, const float* __restrict__ fb2,
                float* __restrict__ out)
{
    extern __shared__ float smem[];
    float* sw1t = smem + OFF_SW1T;
    float* sb1  = smem + OFF_SB1;
    float* xb    = smem + OFF_XB;
    float* s1p   = smem + OFF_S1;
    float* s2p   = smem + OFF_S2;
    float* s4buf = smem + OFF_S4;
    unsigned* mkbuf = (unsigned*)(smem + OFF_MSK);
    int* nact = (int*)(smem + OFF_NACT);
    u16* act = (u16*)(smem + OFF_ACT);

    const int tid  = threadIdx.x;
    const int lane = tid & 31;
    const int warp = tid >> 5;            // 0..3
    const int b = blockIdx.x;             // one sample per CTA

    // ---- conv1 weights/biases into smem ----
    for (int i = tid; i < C1 * K1; i += NTHREADS) {
        int co = i / K1, k = i - co * K1;
        sw1t[k * C1 + co] = w1[i];
    }
    if (tid < C1) sb1[tid] = b1[tid];
    // x prefetch for t=0
    if (warp == 0 && lane < L0)
        xb[lane] = __ldg(&x[b * (L0 * TSTEPS) + lane * TSTEPS]);

    // ---- per-thread register state ----
    // conv1 owned by warps 0,2,3: tix in [0,96), 4 outputs each
    const int tix = (warp == 0 ? 0 : warp - 1) * 32 + lane;   // valid for warp != 1
    float m1r[4] = {0.0f, 0.0f, 0.0f, 0.0f};
    const float b2r = __ldg(&b2v[lane]);
    float m2r[5] = {0.0f, 0.0f, 0.0f, 0.0f, 0.0f};
    const int l02 = warp * 5;                  // conv2: {5,5,5,5}
    const int co3 = ((warp & 1) << 5) | lane;  // conv3: {9,9}
    const int T3  = warp >> 1;
    const float b3r = __ldg(&b3v[co3]);
    float m3r[9];
    #pragma unroll
    for (int q = 0; q < 9; q++) m3r[q] = 0.0f;
    float m4a = 0.0f, m4b = 0.0f;
    float m5r[3] = {0.0f, 0.0f, 0.0f};
    __syncthreads();   // weights + xb(0) visible

    // ---- prologue: conv1(t=0) by warps 0,2,3 ----
    if (warp != 1) {
        const float* xr = xb;   // buf 0
        if (warp == 0 && lane < L0)
            xb[32 + lane] = __ldg(&x[b * (L0 * TSTEPS) + lane * TSTEPS + 1]);
        #pragma unroll
        for (int it = 0; it < 4; it++) {
            int idx = tix + it * 96;
            int l = idx >> 4, co = idx & 15;
            float acc = sb1[co];
            #pragma unroll
            for (int k = 0; k < K1; k++)
                acc = fmaf(sw1t[k * C1 + co], xr[l + k], acc);
            float mn = lif_new_mem(m1r[it], acc);
            m1r[it] = mn;
            s1p[(co >> 1) * S1ROW + l * 2 + (co & 1)] = (mn > 1.0f) ? 1.0f : 0.0f;
        }
    }
    __syncthreads();   // s1(0) ready

    for (int t = 0; t < TSTEPS; t++) {
        // ======== conv2 (16->32, k=5): co=lane, 5 l per thread ========
        {
            u64 acc[5];
            const float* sb = s1p + (l02 & ~1) * 2;
            if (warp & 1)
                conv_pair<5, K2, 8, C2, S1ROW, 1>(g_w2p, sb, lane, pack2(b2r, 0.0f), acc);
            else
                conv_pair<5, K2, 8, C2, S1ROW, 0>(g_w2p, sb, lane, pack2(b2r, 0.0f), acc);
            #pragma unroll
            for (int q = 0; q < 5; q++) {
                float lo, hi; unpack2(acc[q], lo, hi);
                float h = __fadd_rn(lo, hi);
                float mn = lif_new_mem(m2r[q], h);
                m2r[q] = mn;
                s2p[(lane >> 1) * S2ROW + (l02 + q) * 2 + (lane & 1)] = (mn > 1.0f) ? 1.0f : 0.0f;
            }
        }
        __syncthreads();   // S2

        // ======== conv3 (32->64, k=3): co3, 9 l per thread ========
        {
            u64 acc[9];
            if (T3 == 0)
                conv_pair<9, K3, 16, C3, S2ROW, 0>(g_w3p, s2p, co3, pack2(b3r, 0.0f), acc);
            else
                conv_pair<9, K3, 16, C3, S2ROW, 1>(g_w3p, s2p + 8 * 2, co3, pack2(b3r, 0.0f), acc);
            unsigned bits = 0;
            #pragma unroll
            for (int q = 0; q < 9; q++) {
                float lo, hi; unpack2(acc[q], lo, hi);
                float h = __fadd_rn(lo, hi);
                float mn = lif_new_mem(m3r[q], h);
                m3r[q] = mn;
                if (mn > 1.0f) bits |= 1u << q;
            }
            mkbuf[T3 * 64 + co3] = bits;   // exclusive store, no atomics
        }
        __syncthreads();   // S3

        // ======== overlapped slot: warp 1 builds list(t); warps 0,2,3 conv1(t+1) ========
        if (warp == 1) {
            int r0 = 2 * lane, r1 = 2 * lane + 1;
            unsigned m0 = mkbuf[r0] | (mkbuf[64 + r0] << 9);   // 18 bits, l ascending
            unsigned m1 = mkbuf[r1] | (mkbuf[64 + r1] << 9);
            int cnt = __popc(m0) + __popc(m1);
            int pos = cnt;
            #pragma unroll
            for (int o = 1; o < 32; o <<= 1) {
                int v = __shfl_up_sync(0xffffffff, pos, o);
                if (lane >= o) pos += v;
            }
            if (lane == 31) *nact = pos;
            u16* ap = act + (pos - cnt);
            int base0 = r0 * L3;
            while (m0) {
                int l = __ffs(m0) - 1; m0 &= m0 - 1;
                *ap++ = (u16)(base0 + l);
            }
            int base1 = r1 * L3;
            while (m1) {
                int l = __ffs(m1) - 1; m1 &= m1 - 1;
                *ap++ = (u16)(base1 + l);
            }
        } else if (t + 1 < TSTEPS) {
            const float* xr = xb + ((t + 1) & 1) * 32;
            if (warp == 0 && lane < L0 && t + 2 < TSTEPS)
                xb[((t + 2) & 1) * 32 + lane] =
                    __ldg(&x[b * (L0 * TSTEPS) + lane * TSTEPS + t + 2]);
            #pragma unroll
            for (int it = 0; it < 4; it++) {
                int idx = tix + it * 96;
                int l = idx >> 4, co = idx & 15;
                float acc = sb1[co];
                #pragma unroll
                for (int k = 0; k < K1; k++)
                    acc = fmaf(sw1t[k * C1 + co], xr[l + k], acc);
                float mn = lif_new_mem(m1r[it], acc);
                m1r[it] = mn;
                s1p[(co >> 1) * S1ROW + l * 2 + (co & 1)] = (mn > 1.0f) ? 1.0f : 0.0f;
            }
        }
        __syncthreads();   // S3b: list(t) + s1(t+1) ready

        // ======== fc1 (1152->256): 128 threads, 2 outputs each ========
        {
            const int na = *nact;
            u64 acc = __ldg((const u64*)(fb1 + 2 * tid));
            const char* base = (const char*)(g_fw1T + 2 * tid);
            const u64* actq = (const u64*)act;
            int a = 0;
            for (; a + 4 <= na; a += 4) {
                u64 four = actq[a >> 2];
                unsigned i0 = (unsigned)(four & 0xFFFFu);
                unsigned i1 = (unsigned)((four >> 16) & 0xFFFFu);
                unsigned i2 = (unsigned)((four >> 32) & 0xFFFFu);
                unsigned i3 = (unsigned)(four >> 48);
                u64 v0 = ldcg64(base + i0 * (H1 * 4));
                u64 v1 = ldcg64(base + i1 * (H1 * 4));
                u64 v2 = ldcg64(base + i2 * (H1 * 4));
                u64 v3 = ldcg64(base + i3 * (H1 * 4));
                acc = fadd2(acc, v0);
                acc = fadd2(acc, v1);
                acc = fadd2(acc, v2);
                acc = fadd2(acc, v3);
            }
            for (; a < na; a++) {
                unsigned i0 = act[a];
                acc = fadd2(acc, ldcg64(base + i0 * (H1 * 4)));
            }
            float lo, hi; unpack2(acc, lo, hi);
            float mn0 = lif_new_mem(m4a, lo);
            float mn1 = lif_new_mem(m4b, hi);
            m4a = mn0; m4b = mn1;
            *(u64*)(s4buf + 2 * tid) =
                pack2((mn0 > 1.0f) ? 1.0f : 0.0f, (mn1 > 1.0f) ? 1.0f : 0.0f);
        }
        __syncthreads();   // S4

        // ======== fc2 (256->10) + output ========
        {
            #pragma unroll
            for (int i = 0; i < 3; i++) {
                int j = warp + 4 * i;
                if (j < NC) {
                    float acc = 0.0f;
                    #pragma unroll
                    for (int q = 0; q < 8; q++) {
                        int ii = lane + 32 * q;
                        acc = fmaf(__ldg(&fw2[j * H1 + ii]), s4buf[ii], acc);
                    }
                    #pragma unroll
                    for (int o = 16; o > 0; o >>= 1)
                        acc += __shfl_down_sync(0xffffffff, acc, o);
                    if (lane == 0) {
                        acc += __ldg(&fb2[j]);
                        float mn = lif_new_mem(m5r[i], acc);
                        m5r[i] = mn;
                        out[(t * BATCH + b) * NC + j] = (mn > 1.0f) ? 1.0f : 0.0f;
                    }
                }
            }
        }
        // no trailing barrier: fc2 reads only s4buf/fw2; s4's next writer (fc1)
        // is three barriers away; conv2(t+1) reads s1p(t+1), ordered by S4.
    }
}

extern "C" void kernel_launch(void* const* d_in, const int* in_sizes, int n_in,
                              void* d_out, int out_size) {
    const float* x   = (const float*)d_in[0];
    const float* w1  = (const float*)d_in[1];
    const float* b1  = (const float*)d_in[2];
    const float* w2  = (const float*)d_in[3];
    const float* b2  = (const float*)d_in[4];
    const float* w3  = (const float*)d_in[5];
    const float* b3  = (const float*)d_in[6];
    const float* fw1 = (const float*)d_in[7];
    const float* fb1 = (const float*)d_in[8];
    const float* fw2 = (const float*)d_in[9];
    const float* fb2 = (const float*)d_in[10];
    float* out = (float*)d_out;

    cudaFuncSetAttribute(snn_kernel, cudaFuncAttributeMaxDynamicSharedMemorySize, SMEM_BYTES);

    transpose_fw1_kernel<<<(H1 * F1 + 255) / 256, 256>>>(fw1);
    pack_weights_kernel<<<(C3 * C2 * K3 + 255) / 256, 256>>>(w2, w3);
    snn_kernel<<<BATCH, NTHREADS, SMEM_BYTES>>>(x, w1, b1, b2, b3,
                                                fb1, fw2, fb2, out);
}

// round 16
// speedup vs baseline: 1.4666x; 1.3657x over previous
#include <cuda_runtime.h>
#include <cuda_bf16.h>

#define BATCH   1024
#define TSTEPS  100
#define L0      30
#define C1      16
#define L1      24
#define K1      7
#define C2      32
#define L2      20
#define K2      5
#define C3      64
#define L3      18
#define K3      3
#define F1      1152   // 64*18
#define H1      256
#define NC      10

#define NTHREADS 128
#define S1ROW 52       // padded word stride per ci-pair, s1
#define AROW  104      // A im2col row stride in bf16 (96 used + 8 pad); 208B = 13*16

typedef unsigned long long u64;
typedef unsigned short u16;
typedef unsigned u32;

// Transposed fc1 weights: fw1T[i*H1 + j] = fw1[j*F1 + i]
__device__ __align__(16) float g_fw1T[F1 * H1];
// Prepacked conv2 weights (interleaved ci-pairs), shared across CTAs via L1
__device__ __align__(16) float g_w2p[C1 * K2 * C2];
// w3 as m16n8k16 B-fragments, 3 bf16 splits (exact fp32 decomposition):
// entry idx = ((s*6 + kt)*8 + nt)*64 + lane*2 + r  -> u32 = {bf16(k0), bf16(k0+1)}
__device__ __align__(16) u32 g_w3f[3 * 6 * 8 * 64];   // 9216

__global__ void transpose_fw1_kernel(const float* __restrict__ fw1) {
    int idx = blockIdx.x * blockDim.x + threadIdx.x;
    if (idx < H1 * F1) {
        int j = idx / F1;
        int i = idx - j * F1;
        g_fw1T[i * H1 + j] = fw1[idx];
    }
}

__device__ __forceinline__ u16 bf16bits(float f) {
    __nv_bfloat16 b = __float2bfloat16_rn(f);
    return *reinterpret_cast<u16*>(&b);
}
__device__ __forceinline__ float bfval(float f) {
    return __bfloat162float(__float2bfloat16_rn(f));
}

__global__ void pack_weights_kernel(const float* __restrict__ w2,
                                    const float* __restrict__ w3) {
    int idx = blockIdx.x * blockDim.x + threadIdx.x;
    if (idx < C2 * C1 * K2) {
        int co = idx / (C1 * K2);
        int r = idx - co * (C1 * K2);
        int ci = r / K2, k = r - ci * K2;
        g_w2p[(((ci >> 1) * K2 + k) * C2 + co) * 2 + (ci & 1)] = w2[idx];
    }
    if (idx < 9216) {
        int s    = idx / 3072;
        int rem  = idx - s * 3072;
        int kt   = rem / 512;
        int rem2 = rem - kt * 512;
        int nt   = rem2 / 64;
        int rem3 = rem2 - nt * 64;
        int ln   = rem3 >> 1;
        int r    = rem3 & 1;
        int co   = nt * 8 + (ln >> 2);
        u32 vals[2];
        #pragma unroll
        for (int h = 0; h < 2; h++) {
            int kg = kt * 16 + (ln & 3) * 2 + r * 8 + h;   // (k,ci) flat: kg = k3*32 + ci
            int k3 = kg >> 5, ci = kg & 31;
            float w = w3[(co * C2 + ci) * K3 + k3];
            float f0 = bfval(w);
            float f1 = bfval(w - f0);
            float sel = (s == 0) ? w : (s == 1) ? (w - f0) : (w - f0 - f1);
            vals[h] = (u32)bf16bits(sel);
        }
        g_w3f[idx] = vals[0] | (vals[1] << 16);
    }
}

// ---- f32x2 helpers ----
__device__ __forceinline__ u64 ffma2(u64 a, u64 b, u64 c) {
    u64 d; asm("fma.rn.f32x2 %0, %1, %2, %3;" : "=l"(d) : "l"(a), "l"(b), "l"(c)); return d;
}
__device__ __forceinline__ u64 fadd2(u64 a, u64 b) {
    u64 d; asm("add.rn.f32x2 %0, %1, %2;" : "=l"(d) : "l"(a), "l"(b)); return d;
}
__device__ __forceinline__ u64 pack2(float lo, float hi) {
    u64 r; asm("mov.b64 %0, {%1, %2};" : "=l"(r) : "f"(lo), "f"(hi)); return r;
}
__device__ __forceinline__ void unpack2(u64 v, float& lo, float& hi) {
    asm("mov.b64 {%0, %1}, %2;" : "=f"(lo), "=f"(hi) : "l"(v));
}
__device__ __forceinline__ u64 ldcg64(const void* p) {
    u64 d; asm volatile("ld.global.cg.b64 %0, [%1];" : "=l"(d) : "l"(p)); return d;
}

// ---- tensor-core helpers ----
__device__ __forceinline__ void ldsm4(u32* a, u32 addr) {
    asm volatile("ldmatrix.sync.aligned.m8n8.x4.shared.b16 {%0,%1,%2,%3}, [%4];"
                 : "=r"(a[0]), "=r"(a[1]), "=r"(a[2]), "=r"(a[3]) : "r"(addr));
}
__device__ __forceinline__ void mma16816(float* c, const u32* a, const u32* b) {
    asm volatile("mma.sync.aligned.m16n8k16.row.col.f32.bf16.bf16.f32 "
                 "{%0,%1,%2,%3}, {%4,%5,%6,%7}, {%8,%9}, {%0,%1,%2,%3};"
                 : "+f"(c[0]), "+f"(c[1]), "+f"(c[2]), "+f"(c[3])
                 : "r"(a[0]), "r"(a[1]), "r"(a[2]), "r"(a[3]), "r"(b[0]), "r"(b[1]));
}

// LIF: reset from PREVIOUS mem (subtract), spike on new mem.
__device__ __forceinline__ float lif_new_mem(float m_old, float h) {
    float reset = (m_old > 1.0f) ? 1.0f : 0.0f;
    return __fadd_rn(__fadd_rn(__fmul_rn(0.9f, m_old), h), -reset);
}

// Dense conv on f32x2 ci-pairs (conv2); spikes via even-aligned LDS.128 pairs.
template<int LEN, int K, int NP, int COUT, int SROW, int PARITY>
__device__ __forceinline__ void conv_pair(const float* __restrict__ gwp,
                                          const float* __restrict__ sbase,
                                          int co, u64 binit, u64* acc) {
    constexpr int NPAIR = (LEN + K + PARITY) / 2;
    #pragma unroll
    for (int q = 0; q < LEN; q++) acc[q] = binit;
    #pragma unroll 4
    for (int p = 0; p < NP; p++) {
        u64 w[K];
        #pragma unroll
        for (int k = 0; k < K; k++)
            w[k] = __ldg((const u64*)(gwp + ((p * K + k) * COUT + co) * 2));
        const ulonglong2* sp = (const ulonglong2*)(sbase + p * SROW);
        #pragma unroll
        for (int dp = 0; dp < NPAIR; dp++) {
            ulonglong2 v = sp[dp];
            #pragma unroll
            for (int k = 0; k < K; k++) {
                int q0 = 2 * dp - PARITY - k;
                if (q0 >= 0 && q0 < LEN) acc[q0] = ffma2(w[k], v.x, acc[q0]);
            }
            #pragma unroll
            for (int k = 0; k < K; k++) {
                int q1 = 2 * dp + 1 - PARITY - k;
                if (q1 >= 0 && q1 < LEN) acc[q1] = ffma2(w[k], v.y, acc[q1]);
            }
        }
    }
}

// smem layout (words), one sample per CTA
#define OFF_SW1T 0        // 112
#define OFF_SB1  112      // 16
#define OFF_XB   128      // 64
#define OFF_S1   192      // 416 (16B aligned)
#define OFF_A    608      // 1664: im2col bf16 [32 rows][104 bf16] (byte 2432, 16B aligned)
#define OFF_S4   2272     // 256
#define OFF_MSK  2528     // 64: mask3[co] (18 bits each)
#define OFF_NACT 2592     // 2
#define OFF_ACT  2594     // 576 words = 1152 u16 (byte 10376, 8B aligned)
#define SMEM_WORDS 3170
#define SMEM_BYTES (SMEM_WORDS * 4)

__global__ __launch_bounds__(NTHREADS, 7)
void snn_kernel(const float* __restrict__ x,
                const float* __restrict__ w1, const float* __restrict__ b1,
                const float* __restrict__ b2v, const float* __restrict__ b3v,
                const float* __restrict__ fb1,
                const float* __restrict__ fw2, const float* __restrict__ fb2,
                float* __restrict__ out)
{
    extern __shared__ float smem[];
    float* sw1t = smem + OFF_SW1T;
    float* sb1  = smem + OFF_SB1;
    float* xb    = smem + OFF_XB;
    float* s1p   = smem + OFF_S1;
    u16*   Au    = (u16*)(smem + OFF_A);
    float* s4buf = smem + OFF_S4;
    u32* mask3 = (u32*)(smem + OFF_MSK);
    int* nact = (int*)(smem + OFF_NACT);
    u16* act = (u16*)(smem + OFF_ACT);

    const int tid  = threadIdx.x;
    const int lane = tid & 31;
    const int warp = tid >> 5;            // 0..3
    const int b = blockIdx.x;             // one sample per CTA

    // ---- init: conv1 weights/biases, zero A + mask3 ----
    for (int i = tid; i < C1 * K1; i += NTHREADS) {
        int co = i / K1, k = i - co * K1;
        sw1t[k * C1 + co] = w1[i];
    }
    if (tid < C1) sb1[tid] = b1[tid];
    for (int i = tid; i < 32 * AROW / 2; i += NTHREADS)   // zero whole A (u32 strides)
        ((u32*)Au)[i] = 0u;
    if (tid < C3) mask3[tid] = 0u;
    if (warp == 0 && lane < L0)
        xb[lane] = __ldg(&x[b * (L0 * TSTEPS) + lane * TSTEPS]);

    // ---- per-thread register state ----
    float m1r[3] = {0.0f, 0.0f, 0.0f};
    const float b2r = __ldg(&b2v[lane]);
    float m2r[5] = {0.0f, 0.0f, 0.0f, 0.0f, 0.0f};
    const int l02 = warp * 5;                  // conv2: {5,5,5,5}
    // conv3 HMMA: warp covers co [16*warp, 16*warp+16)
    const int tq = lane >> 2;                  // fragment row
    const int tc = (lane & 3) * 2;             // fragment col pair
    float bco[4];                              // biases for co00,co01,co10,co11
    #pragma unroll
    for (int i2 = 0; i2 < 4; i2++)
        bco[i2] = __ldg(&b3v[16 * warp + (i2 >> 1) * 8 + tc + (i2 & 1)]);
    float m3a[8];                              // mt0: [ntl][reg]
    #pragma unroll
    for (int q = 0; q < 8; q++) m3a[q] = 0.0f;
    float m3b[4] = {0.0f, 0.0f, 0.0f, 0.0f};   // mt1 (tq<2): [ntl][reg0/1]
    float m4a = 0.0f, m4b = 0.0f;
    float m5r[3] = {0.0f, 0.0f, 0.0f};
    // ldmatrix per-lane base address (u32 shared space)
    const u32 Abase = (u32)__cvta_generic_to_shared(Au);
    const u32 aAddrBase = Abase + (u32)((lane & 15) * (AROW * 2) + (lane >> 4) * 16);
    __syncthreads();

    for (int t = 0; t < TSTEPS; t++) {
        // ======== conv1 (1->16, k=7): 128 threads, 3 outputs each ========
        {
            const float* xr = xb + (t & 1) * 32;
            if (warp == 0 && lane < L0 && t + 1 < TSTEPS)
                xb[((t + 1) & 1) * 32 + lane] =
                    __ldg(&x[b * (L0 * TSTEPS) + lane * TSTEPS + t + 1]);
            #pragma unroll
            for (int it = 0; it < 3; it++) {
                int idx = tid + it * 128;
                int l = idx >> 4, co = idx & 15;
                float acc = sb1[co];
                #pragma unroll
                for (int k = 0; k < K1; k++)
                    acc = fmaf(sw1t[k * C1 + co], xr[l + k], acc);
                float mn = lif_new_mem(m1r[it], acc);
                m1r[it] = mn;
                s1p[(co >> 1) * S1ROW + l * 2 + (co & 1)] = (mn > 1.0f) ? 1.0f : 0.0f;
            }
        }
        __syncthreads();   // S1

        // ======== conv2 (16->32, k=5): co=lane, 5 l; writes bf16 im2col A ========
        {
            u64 acc[5];
            const float* sb = s1p + (l02 & ~1) * 2;
            if (warp & 1)
                conv_pair<5, K2, 8, C2, S1ROW, 1>(g_w2p, sb, lane, pack2(b2r, 0.0f), acc);
            else
                conv_pair<5, K2, 8, C2, S1ROW, 0>(g_w2p, sb, lane, pack2(b2r, 0.0f), acc);
            #pragma unroll
            for (int q = 0; q < 5; q++) {
                float lo, hi; unpack2(acc[q], lo, hi);
                float h = __fadd_rn(lo, hi);
                float mn = lif_new_mem(m2r[q], h);
                m2r[q] = mn;
                u16 sp16 = (mn > 1.0f) ? (u16)0x3F80 : (u16)0;
                int ls = l02 + q;
                #pragma unroll
                for (int k3 = 0; k3 < 3; k3++) {
                    int r = ls - k3;
                    if (r >= 0 && r <= 17)
                        Au[r * AROW + k3 * 32 + lane] = sp16;   // A[l][k3*32+ci]
                }
            }
        }
        __syncthreads();   // S2

        // ======== conv3 via tensor cores: C[32l x 16co/warp] = A x w3f ========
        {
            float c[2][2][4];   // [ntl][mt][reg]
            #pragma unroll
            for (int i2 = 0; i2 < 2; i2++)
                #pragma unroll
                for (int j2 = 0; j2 < 2; j2++)
                    #pragma unroll
                    for (int r = 0; r < 4; r++) c[i2][j2][r] = 0.0f;
            #pragma unroll
            for (int kt = 0; kt < 6; kt++) {
                u32 afr[2][4];
                ldsm4(afr[0], aAddrBase + kt * 32);
                ldsm4(afr[1], aAddrBase + 16 * (AROW * 2) + kt * 32);
                #pragma unroll
                for (int s = 0; s < 3; s++) {
                    #pragma unroll
                    for (int ntl = 0; ntl < 2; ntl++) {
                        int nt = 2 * warp + ntl;
                        u64 bv = __ldg((const u64*)(g_w3f +
                                 (((s * 6 + kt) * 8 + nt) << 6) + (lane << 1)));
                        u32 bfr[2];
                        bfr[0] = (u32)bv;
                        bfr[1] = (u32)(bv >> 32);
                        mma16816(c[ntl][0], afr[0], bfr);
                        mma16816(c[ntl][1], afr[1], bfr);
                    }
                }
            }
            // epilogue: LIF + spike bits (l = row, co = 16*warp + ntl*8 + tc + colbit)
            u32 bits[4] = {0u, 0u, 0u, 0u};
            #pragma unroll
            for (int ntl = 0; ntl < 2; ntl++) {
                #pragma unroll
                for (int reg = 0; reg < 4; reg++) {
                    int l = tq + (reg >> 1) * 8;           // 0..15
                    int bidx = ntl * 2 + (reg & 1);
                    float h = bco[bidx] + c[ntl][0][reg];
                    float mn = lif_new_mem(m3a[ntl * 4 + reg], h);
                    m3a[ntl * 4 + reg] = mn;
                    if (mn > 1.0f) bits[bidx] |= 1u << l;
                }
                if (tq < 2) {
                    #pragma unroll
                    for (int reg = 0; reg < 2; reg++) {
                        int l = 16 + tq;                   // 16,17
                        int bidx = ntl * 2 + reg;
                        float h = bco[bidx] + c[ntl][1][reg];
                        float mn = lif_new_mem(m3b[ntl * 2 + reg], h);
                        m3b[ntl * 2 + reg] = mn;
                        if (mn > 1.0f) bits[bidx] |= 1u << l;
                    }
                }
            }
            #pragma unroll
            for (int i2 = 0; i2 < 4; i2++) {
                int co = 16 * warp + (i2 >> 1) * 8 + tc + (i2 & 1);
                if (bits[i2]) atomicOr(&mask3[co], bits[i2]);
            }
        }
        __syncthreads();   // S3

        // ======== build active-index list (warp 1) ========
        if (warp == 1) {
            int r0 = 2 * lane, r1 = 2 * lane + 1;
            u32 m0 = mask3[r0];   // 18 bits, l ascending
            u32 m1 = mask3[r1];
            int cnt = __popc(m0) + __popc(m1);
            int pos = cnt;
            #pragma unroll
            for (int o = 1; o < 32; o <<= 1) {
                int v = __shfl_up_sync(0xffffffff, pos, o);
                if (lane >= o) pos += v;
            }
            if (lane == 31) *nact = pos;
            u16* ap = act + (pos - cnt);
            int base0 = r0 * L3;
            while (m0) {
                int l = __ffs(m0) - 1; m0 &= m0 - 1;
                *ap++ = (u16)(base0 + l);
            }
            int base1 = r1 * L3;
            while (m1) {
                int l = __ffs(m1) - 1; m1 &= m1 - 1;
                *ap++ = (u16)(base1 + l);
            }
        }
        __syncthreads();   // S3b

        // ======== fc1 (1152->256): 128 threads, 2 outputs each ========
        {
            const int na = *nact;
            u64 acc = __ldg((const u64*)(fb1 + 2 * tid));
            const char* base = (const char*)(g_fw1T + 2 * tid);
            const u64* actq = (const u64*)act;
            int a = 0;
            for (; a + 4 <= na; a += 4) {
                u64 four = actq[a >> 2];
                u32 i0 = (u32)(four & 0xFFFFu);
                u32 i1 = (u32)((four >> 16) & 0xFFFFu);
                u32 i2 = (u32)((four >> 32) & 0xFFFFu);
                u32 i3 = (u32)(four >> 48);
                u64 v0 = ldcg64(base + i0 * (H1 * 4));
                u64 v1 = ldcg64(base + i1 * (H1 * 4));
                u64 v2 = ldcg64(base + i2 * (H1 * 4));
                u64 v3 = ldcg64(base + i3 * (H1 * 4));
                acc = fadd2(acc, v0);
                acc = fadd2(acc, v1);
                acc = fadd2(acc, v2);
                acc = fadd2(acc, v3);
            }
            for (; a < na; a++) {
                u32 i0 = act[a];
                acc = fadd2(acc, ldcg64(base + i0 * (H1 * 4)));
            }
            float lo, hi; unpack2(acc, lo, hi);
            float mn0 = lif_new_mem(m4a, lo);
            float mn1 = lif_new_mem(m4b, hi);
            m4a = mn0; m4b = mn1;
            *(u64*)(s4buf + 2 * tid) =
                pack2((mn0 > 1.0f) ? 1.0f : 0.0f, (mn1 > 1.0f) ? 1.0f : 0.0f);
        }
        __syncthreads();   // S4

        // ======== fc2 (256->10) + output; also re-zero mask3 for next t ========
        {
            if (tid < C3) mask3[tid] = 0u;   // after S4 (build+conv3 done), before next S2
            #pragma unroll
            for (int i = 0; i < 3; i++) {
                int j = warp + 4 * i;
                if (j < NC) {
                    float acc = 0.0f;
                    #pragma unroll
                    for (int q = 0; q < 8; q++) {
                        int ii = lane + 32 * q;
                        acc = fmaf(__ldg(&fw2[j * H1 + ii]), s4buf[ii], acc);
                    }
                    #pragma unroll
                    for (int o = 16; o > 0; o >>= 1)
                        acc += __shfl_down_sync(0xffffffff, acc, o);
                    if (lane == 0) {
                        acc += __ldg(&fb2[j]);
                        float mn = lif_new_mem(m5r[i], acc);
                        m5r[i] = mn;
                        out[(t * BATCH + b) * NC + j] = (mn > 1.0f) ? 1.0f : 0.0f;
                    }
                }
            }
        }
        // no trailing barrier: mask3 zero + fc2 are separated from next conv3
        // atomics by S1 and S2; s4's next writer (fc1) is three barriers away.
    }
}

extern "C" void kernel_launch(void* const* d_in, const int* in_sizes, int n_in,
                              void* d_out, int out_size) {
    const float* x   = (const float*)d_in[0];
    const float* w1  = (const float*)d_in[1];
    const float* b1  = (const float*)d_in[2];
    const float* w2  = (const float*)d_in[3];
    const float* b2  = (const float*)d_in[4];
    const float* w3  = (const float*)d_in[5];
    const float* b3  = (const float*)d_in[6];
    const float* fw1 = (const float*)d_in[7];
    const float* fb1 = (const float*)d_in[8];
    const float* fw2 = (const float*)d_in[9];
    const float* fb2 = (const float*)d_in[10];
    float* out = (float*)d_out;

    cudaFuncSetAttribute(snn_kernel, cudaFuncAttributeMaxDynamicSharedMemorySize, SMEM_BYTES);

    transpose_fw1_kernel<<<(H1 * F1 + 255) / 256, 256>>>(fw1);
    pack_weights_kernel<<<(9216 + 255) / 256, 256>>>(w2, w3);
    snn_kernel<<<BATCH, NTHREADS, SMEM_BYTES>>>(x, w1, b1, b2, b3,
                                                fb1, fw2, fb2, out);
}

// round 17
// speedup vs baseline: 1.7101x; 1.1660x over previous
#include <cuda_runtime.h>
#include <cuda_bf16.h>

#define BATCH   1024
#define TSTEPS  100
#define L0      30
#define C1      16
#define L1      24
#define K1      7
#define C2      32
#define L2      20
#define K2      5
#define C3      64
#define L3      18
#define K3      3
#define F1      1152   // 64*18
#define H1      256
#define NC      10

#define NTHREADS 128
#define AROW  104      // im2col row stride in bf16 (96 used + 8 pad); 208B

typedef unsigned long long u64;
typedef unsigned short u16;
typedef unsigned u32;

// Transposed fc1 weights: fw1T[i*H1 + j] = fw1[j*F1 + i]
__device__ __align__(16) float g_fw1T[F1 * H1];
// w2 as m16n8k16 B-fragments, 3 bf16 splits (exact fp32 decomposition):
// idx = ((s*6 + kt)*4 + nt)*64 + lane*2 + r ; kg = k2*16+ci (80 used, pad 96)
__device__ __align__(16) u32 g_w2f[3 * 6 * 4 * 64];   // 4608
// w3 as m16n8k16 B-fragments, 3 bf16 splits:
// idx = ((s*6 + kt)*8 + nt)*64 + lane*2 + r ; kg = k3*32+ci (96)
__device__ __align__(16) u32 g_w3f[3 * 6 * 8 * 64];   // 9216

__global__ void transpose_fw1_kernel(const float* __restrict__ fw1) {
    int idx = blockIdx.x * blockDim.x + threadIdx.x;
    if (idx < H1 * F1) {
        int j = idx / F1;
        int i = idx - j * F1;
        g_fw1T[i * H1 + j] = fw1[idx];
    }
}

__device__ __forceinline__ u16 bf16bits(float f) {
    __nv_bfloat16 b = __float2bfloat16_rn(f);
    return *reinterpret_cast<u16*>(&b);
}
__device__ __forceinline__ float bfval(float f) {
    return __bfloat162float(__float2bfloat16_rn(f));
}
__device__ __forceinline__ u32 split3_bits(float w, int s) {
    float f0 = bfval(w);
    float f1 = bfval(w - f0);
    float sel = (s == 0) ? w : (s == 1) ? (w - f0) : (w - f0 - f1);
    return (u32)bf16bits(sel);
}

__global__ void pack_weights_kernel(const float* __restrict__ w2,
                                    const float* __restrict__ w3) {
    int idx = blockIdx.x * blockDim.x + threadIdx.x;
    // ---- w2 fragments (4608) ----
    if (idx < 4608) {
        int s    = idx / 1536;
        int rem  = idx - s * 1536;
        int kt   = rem / 256;
        int rem2 = rem - kt * 256;
        int nt   = rem2 / 64;
        int rem3 = rem2 - nt * 64;
        int ln   = rem3 >> 1;
        int r    = rem3 & 1;
        int co   = nt * 8 + (ln >> 2);
        u32 vals[2];
        #pragma unroll
        for (int h = 0; h < 2; h++) {
            int kg = kt * 16 + (ln & 3) * 2 + r * 8 + h;   // kg = k2*16 + ci
            u32 v = 0;
            if (kg < 80) {
                int k2 = kg >> 4, ci = kg & 15;
                v = split3_bits(w2[(co * C1 + ci) * K2 + k2], s);
            }
            vals[h] = v;
        }
        g_w2f[idx] = vals[0] | (vals[1] << 16);
    }
    // ---- w3 fragments (9216) ----
    if (idx < 9216) {
        int s    = idx / 3072;
        int rem  = idx - s * 3072;
        int kt   = rem / 512;
        int rem2 = rem - kt * 512;
        int nt   = rem2 / 64;
        int rem3 = rem2 - nt * 64;
        int ln   = rem3 >> 1;
        int r    = rem3 & 1;
        int co   = nt * 8 + (ln >> 2);
        u32 vals[2];
        #pragma unroll
        for (int h = 0; h < 2; h++) {
            int kg = kt * 16 + (ln & 3) * 2 + r * 8 + h;   // kg = k3*32 + ci
            int k3 = kg >> 5, ci = kg & 31;
            vals[h] = split3_bits(w3[(co * C2 + ci) * K3 + k3], s);
        }
        g_w3f[idx] = vals[0] | (vals[1] << 16);
    }
}

// ---- f32x2 helpers ----
__device__ __forceinline__ u64 fadd2(u64 a, u64 b) {
    u64 d; asm("add.rn.f32x2 %0, %1, %2;" : "=l"(d) : "l"(a), "l"(b)); return d;
}
__device__ __forceinline__ u64 pack2(float lo, float hi) {
    u64 r; asm("mov.b64 %0, {%1, %2};" : "=l"(r) : "f"(lo), "f"(hi)); return r;
}
__device__ __forceinline__ void unpack2(u64 v, float& lo, float& hi) {
    asm("mov.b64 {%0, %1}, %2;" : "=f"(lo), "=f"(hi) : "l"(v));
}
__device__ __forceinline__ u64 ldcg64(const void* p) {
    u64 d; asm volatile("ld.global.cg.b64 %0, [%1];" : "=l"(d) : "l"(p)); return d;
}

// ---- tensor-core helpers ----
__device__ __forceinline__ void ldsm4(u32* a, u32 addr) {
    asm volatile("ldmatrix.sync.aligned.m8n8.x4.shared.b16 {%0,%1,%2,%3}, [%4];"
                 : "=r"(a[0]), "=r"(a[1]), "=r"(a[2]), "=r"(a[3]) : "r"(addr));
}
__device__ __forceinline__ void mma16816(float* c, const u32* a, const u32* b) {
    asm volatile("mma.sync.aligned.m16n8k16.row.col.f32.bf16.bf16.f32 "
                 "{%0,%1,%2,%3}, {%4,%5,%6,%7}, {%8,%9}, {%0,%1,%2,%3};"
                 : "+f"(c[0]), "+f"(c[1]), "+f"(c[2]), "+f"(c[3])
                 : "r"(a[0]), "r"(a[1]), "r"(a[2]), "r"(a[3]), "r"(b[0]), "r"(b[1]));
}

// LIF: reset from PREVIOUS mem (subtract), spike on new mem.
__device__ __forceinline__ float lif_new_mem(float m_old, float h) {
    float reset = (m_old > 1.0f) ? 1.0f : 0.0f;
    return __fadd_rn(__fadd_rn(__fmul_rn(0.9f, m_old), h), -reset);
}

// smem layout (words), one sample per CTA
#define OFF_SW1T 0        // 112
#define OFF_SB1  112      // 16
#define OFF_XB   128      // 64
#define OFF_A1   192      // 1664: im2col bf16 [32][104]  (byte 768, 16B aligned)
#define OFF_A3   1856     // 1664: im2col bf16 [32][104]  (byte 7424, 16B aligned)
#define OFF_S4   3520     // 256
#define OFF_MSK  3776     // 64: mask3[co] (18 bits each)
#define OFF_NACT 3840     // 2
#define OFF_ACT  3842     // 576 words = 1152 u16 (byte 15368, 8B aligned)
#define SMEM_WORDS 4418
#define SMEM_BYTES (SMEM_WORDS * 4)

__global__ __launch_bounds__(NTHREADS, 7)
void snn_kernel(const float* __restrict__ x,
                const float* __restrict__ w1, const float* __restrict__ b1,
                const float* __restrict__ b2v, const float* __restrict__ b3v,
                const float* __restrict__ fb1,
                const float* __restrict__ fw2, const float* __restrict__ fb2,
                float* __restrict__ out)
{
    extern __shared__ float smem[];
    float* sw1t = smem + OFF_SW1T;
    float* sb1  = smem + OFF_SB1;
    float* xb    = smem + OFF_XB;
    u16*   Au1   = (u16*)(smem + OFF_A1);
    u16*   Au3   = (u16*)(smem + OFF_A3);
    float* s4buf = smem + OFF_S4;
    u32* mask3 = (u32*)(smem + OFF_MSK);
    int* nact = (int*)(smem + OFF_NACT);
    u16* act = (u16*)(smem + OFF_ACT);

    const int tid  = threadIdx.x;
    const int lane = tid & 31;
    const int warp = tid >> 5;            // 0..3
    const int b = blockIdx.x;             // one sample per CTA

    // ---- init ----
    for (int i = tid; i < C1 * K1; i += NTHREADS) {
        int co = i / K1, k = i - co * K1;
        sw1t[k * C1 + co] = w1[i];
    }
    if (tid < C1) sb1[tid] = b1[tid];
    for (int i = tid; i < 32 * AROW / 2; i += NTHREADS) {
        ((u32*)Au1)[i] = 0u;
        ((u32*)Au3)[i] = 0u;
    }
    if (tid < C3) mask3[tid] = 0u;
    if (warp == 0 && lane < L0)
        xb[lane] = __ldg(&x[b * (L0 * TSTEPS) + lane * TSTEPS]);

    // ---- per-thread register state ----
    float m1r[3] = {0.0f, 0.0f, 0.0f};
    const int tq = lane >> 2;                  // fragment row
    const int tc = (lane & 3) * 2;             // fragment col pair
    // conv2 HMMA: warp covers co [8*warp, 8*warp+8)
    float bco2[2];
    #pragma unroll
    for (int i2 = 0; i2 < 2; i2++)
        bco2[i2] = __ldg(&b2v[8 * warp + tc + i2]);
    float m2a[4] = {0.0f, 0.0f, 0.0f, 0.0f};   // mt0 regs
    float m2b[2] = {0.0f, 0.0f};               // mt1 regs (tq<4)
    // conv3 HMMA: warp covers co [16*warp, 16*warp+16)
    float bco3[4];
    #pragma unroll
    for (int i2 = 0; i2 < 4; i2++)
        bco3[i2] = __ldg(&b3v[16 * warp + (i2 >> 1) * 8 + tc + (i2 & 1)]);
    float m3a[8];
    #pragma unroll
    for (int q = 0; q < 8; q++) m3a[q] = 0.0f;
    float m3b[4] = {0.0f, 0.0f, 0.0f, 0.0f};
    float m4a = 0.0f, m4b = 0.0f;
    float m5r[3] = {0.0f, 0.0f, 0.0f};
    // ldmatrix per-lane base addresses
    const u32 a1Addr = (u32)__cvta_generic_to_shared(Au1)
                     + (u32)((lane & 15) * (AROW * 2) + (lane >> 4) * 16);
    const u32 a3Addr = (u32)__cvta_generic_to_shared(Au3)
                     + (u32)((lane & 15) * (AROW * 2) + (lane >> 4) * 16);
    __syncthreads();

    for (int t = 0; t < TSTEPS; t++) {
        // ======== conv1 (1->16, k=7): 128 threads, 3 outputs each -> A1 im2col ========
        {
            const float* xr = xb + (t & 1) * 32;
            if (warp == 0 && lane < L0 && t + 1 < TSTEPS)
                xb[((t + 1) & 1) * 32 + lane] =
                    __ldg(&x[b * (L0 * TSTEPS) + lane * TSTEPS + t + 1]);
            #pragma unroll
            for (int it = 0; it < 3; it++) {
                int idx = tid + it * 128;
                int l = idx >> 4, co = idx & 15;
                float acc = sb1[co];
                #pragma unroll
                for (int k = 0; k < K1; k++)
                    acc = fmaf(sw1t[k * C1 + co], xr[l + k], acc);
                float mn = lif_new_mem(m1r[it], acc);
                m1r[it] = mn;
                u16 sp16 = (mn > 1.0f) ? (u16)0x3F80 : (u16)0;
                #pragma unroll
                for (int k2 = 0; k2 < K2; k2++) {
                    int r = l - k2;
                    if (r >= 0 && r < L2)
                        Au1[r * AROW + k2 * 16 + co] = sp16;   // A1[l2][k2*16+ci]
                }
            }
        }
        __syncthreads();   // S1

        // ======== conv2 via tensor cores: C[32l x 8co/warp] = A1 x w2f ========
        {
            float c[2][4];   // [mt][reg]
            #pragma unroll
            for (int j2 = 0; j2 < 2; j2++)
                #pragma unroll
                for (int r = 0; r < 4; r++) c[j2][r] = 0.0f;
            #pragma unroll
            for (int kt = 0; kt < 6; kt++) {
                u32 afr[2][4];
                ldsm4(afr[0], a1Addr + kt * 32);
                ldsm4(afr[1], a1Addr + 16 * (AROW * 2) + kt * 32);
                #pragma unroll
                for (int s = 0; s < 3; s++) {
                    u64 bv = __ldg((const u64*)(g_w2f +
                             (((s * 6 + kt) * 4 + warp) << 6) + (lane << 1)));
                    u32 bfr[2];
                    bfr[0] = (u32)bv;
                    bfr[1] = (u32)(bv >> 32);
                    mma16816(c[0], afr[0], bfr);
                    mma16816(c[1], afr[1], bfr);
                }
            }
            // epilogue: LIF + write A3 im2col (l = row, co = 8*warp + tc + colbit)
            #pragma unroll
            for (int reg = 0; reg < 4; reg++) {
                int l = tq + (reg >> 1) * 8;               // 0..15
                int co = 8 * warp + tc + (reg & 1);
                float h = bco2[reg & 1] + c[0][reg];
                float mn = lif_new_mem(m2a[reg], h);
                m2a[reg] = mn;
                u16 sp16 = (mn > 1.0f) ? (u16)0x3F80 : (u16)0;
                #pragma unroll
                for (int k3 = 0; k3 < K3; k3++) {
                    int r = l - k3;
                    if (r >= 0 && r < L3)
                        Au3[r * AROW + k3 * 32 + co] = sp16;
                }
            }
            if (tq < 4) {
                #pragma unroll
                for (int reg = 0; reg < 2; reg++) {
                    int l = 16 + tq;                       // 16..19
                    int co = 8 * warp + tc + reg;
                    float h = bco2[reg] + c[1][reg];
                    float mn = lif_new_mem(m2b[reg], h);
                    m2b[reg] = mn;
                    u16 sp16 = (mn > 1.0f) ? (u16)0x3F80 : (u16)0;
                    #pragma unroll
                    for (int k3 = 0; k3 < K3; k3++) {
                        int r = l - k3;
                        if (r >= 0 && r < L3)
                            Au3[r * AROW + k3 * 32 + co] = sp16;
                    }
                }
            }
        }
        __syncthreads();   // S2

        // ======== conv3 via tensor cores: C[32l x 16co/warp] = A3 x w3f ========
        {
            float c[2][2][4];   // [ntl][mt][reg]
            #pragma unroll
            for (int i2 = 0; i2 < 2; i2++)
                #pragma unroll
                for (int j2 = 0; j2 < 2; j2++)
                    #pragma unroll
                    for (int r = 0; r < 4; r++) c[i2][j2][r] = 0.0f;
            #pragma unroll
            for (int kt = 0; kt < 6; kt++) {
                u32 afr[2][4];
                ldsm4(afr[0], a3Addr + kt * 32);
                ldsm4(afr[1], a3Addr + 16 * (AROW * 2) + kt * 32);
                #pragma unroll
                for (int s = 0; s < 3; s++) {
                    #pragma unroll
                    for (int ntl = 0; ntl < 2; ntl++) {
                        int nt = 2 * warp + ntl;
                        u64 bv = __ldg((const u64*)(g_w3f +
                                 (((s * 6 + kt) * 8 + nt) << 6) + (lane << 1)));
                        u32 bfr[2];
                        bfr[0] = (u32)bv;
                        bfr[1] = (u32)(bv >> 32);
                        mma16816(c[ntl][0], afr[0], bfr);
                        mma16816(c[ntl][1], afr[1], bfr);
                    }
                }
            }
            // epilogue: LIF + spike bits (l = row, co = 16*warp + ntl*8 + tc + colbit)
            u32 bits[4] = {0u, 0u, 0u, 0u};
            #pragma unroll
            for (int ntl = 0; ntl < 2; ntl++) {
                #pragma unroll
                for (int reg = 0; reg < 4; reg++) {
                    int l = tq + (reg >> 1) * 8;           // 0..15
                    int bidx = ntl * 2 + (reg & 1);
                    float h = bco3[bidx] + c[ntl][0][reg];
                    float mn = lif_new_mem(m3a[ntl * 4 + reg], h);
                    m3a[ntl * 4 + reg] = mn;
                    if (mn > 1.0f) bits[bidx] |= 1u << l;
                }
                if (tq < 2) {
                    #pragma unroll
                    for (int reg = 0; reg < 2; reg++) {
                        int l = 16 + tq;                   // 16,17
                        int bidx = ntl * 2 + reg;
                        float h = bco3[bidx] + c[ntl][1][reg];
                        float mn = lif_new_mem(m3b[ntl * 2 + reg], h);
                        m3b[ntl * 2 + reg] = mn;
                        if (mn > 1.0f) bits[bidx] |= 1u << l;
                    }
                }
            }
            #pragma unroll
            for (int i2 = 0; i2 < 4; i2++) {
                int co = 16 * warp + (i2 >> 1) * 8 + tc + (i2 & 1);
                if (bits[i2]) atomicOr(&mask3[co], bits[i2]);
            }
        }
        __syncthreads();   // S3

        // ======== build active-index list (warp 1) ========
        if (warp == 1) {
            int r0 = 2 * lane, r1 = 2 * lane + 1;
            u32 m0 = mask3[r0];   // 18 bits, l ascending
            u32 m1 = mask3[r1];
            int cnt = __popc(m0) + __popc(m1);
            int pos = cnt;
            #pragma unroll
            for (int o = 1; o < 32; o <<= 1) {
                int v = __shfl_up_sync(0xffffffff, pos, o);
                if (lane >= o) pos += v;
            }
            if (lane == 31) *nact = pos;
            u16* ap = act + (pos - cnt);
            int base0 = r0 * L3;
            while (m0) {
                int l = __ffs(m0) - 1; m0 &= m0 - 1;
                *ap++ = (u16)(base0 + l);
            }
            int base1 = r1 * L3;
            while (m1) {
                int l = __ffs(m1) - 1; m1 &= m1 - 1;
                *ap++ = (u16)(base1 + l);
            }
        }
        __syncthreads();   // S3b

        // ======== fc1 (1152->256): 128 threads, 2 outputs each ========
        {
            const int na = *nact;
            u64 acc = __ldg((const u64*)(fb1 + 2 * tid));
            const char* base = (const char*)(g_fw1T + 2 * tid);
            const u64* actq = (const u64*)act;
            int a = 0;
            for (; a + 4 <= na; a += 4) {
                u64 four = actq[a >> 2];
                u32 i0 = (u32)(four & 0xFFFFu);
                u32 i1 = (u32)((four >> 16) & 0xFFFFu);
                u32 i2 = (u32)((four >> 32) & 0xFFFFu);
                u32 i3 = (u32)(four >> 48);
                u64 v0 = ldcg64(base + i0 * (H1 * 4));
                u64 v1 = ldcg64(base + i1 * (H1 * 4));
                u64 v2 = ldcg64(base + i2 * (H1 * 4));
                u64 v3 = ldcg64(base + i3 * (H1 * 4));
                acc = fadd2(acc, v0);
                acc = fadd2(acc, v1);
                acc = fadd2(acc, v2);
                acc = fadd2(acc, v3);
            }
            for (; a < na; a++) {
                u32 i0 = act[a];
                acc = fadd2(acc, ldcg64(base + i0 * (H1 * 4)));
            }
            float lo, hi; unpack2(acc, lo, hi);
            float mn0 = lif_new_mem(m4a, lo);
            float mn1 = lif_new_mem(m4b, hi);
            m4a = mn0; m4b = mn1;
            *(u64*)(s4buf + 2 * tid) =
                pack2((mn0 > 1.0f) ? 1.0f : 0.0f, (mn1 > 1.0f) ? 1.0f : 0.0f);
        }
        __syncthreads();   // S4

        // ======== fc2 (256->10) + output; re-zero mask3 for next t ========
        {
            if (tid < C3) mask3[tid] = 0u;
            #pragma unroll
            for (int i = 0; i < 3; i++) {
                int j = warp + 4 * i;
                if (j < NC) {
                    float acc = 0.0f;
                    #pragma unroll
                    for (int q = 0; q < 8; q++) {
                        int ii = lane + 32 * q;
                        acc = fmaf(__ldg(&fw2[j * H1 + ii]), s4buf[ii], acc);
                    }
                    #pragma unroll
                    for (int o = 16; o > 0; o >>= 1)
                        acc += __shfl_down_sync(0xffffffff, acc, o);
                    if (lane == 0) {
                        acc += __ldg(&fb2[j]);
                        float mn = lif_new_mem(m5r[i], acc);
                        m5r[i] = mn;
                        out[(t * BATCH + b) * NC + j] = (mn > 1.0f) ? 1.0f : 0.0f;
                    }
                }
            }
        }
        // no trailing barrier: mask3 zero + fc2 are separated from the next
        // conv3 atomics by S1 and S2; s4's next writer (fc1) is three barriers away.
    }
}

extern "C" void kernel_launch(void* const* d_in, const int* in_sizes, int n_in,
                              void* d_out, int out_size) {
    const float* x   = (const float*)d_in[0];
    const float* w1  = (const float*)d_in[1];
    const float* b1  = (const float*)d_in[2];
    const float* w2  = (const float*)d_in[3];
    const float* b2  = (const float*)d_in[4];
    const float* w3  = (const float*)d_in[5];
    const float* b3  = (const float*)d_in[6];
    const float* fw1 = (const float*)d_in[7];
    const float* fb1 = (const float*)d_in[8];
    const float* fw2 = (const float*)d_in[9];
    const float* fb2 = (const float*)d_in[10];
    float* out = (float*)d_out;

    cudaFuncSetAttribute(snn_kernel, cudaFuncAttributeMaxDynamicSharedMemorySize, SMEM_BYTES);

    transpose_fw1_kernel<<<(H1 * F1 + 255) / 256, 256>>>(fw1);
    pack_weights_kernel<<<(9216 + 255) / 256, 256>>>(w2, w3);
    snn_kernel<<<BATCH, NTHREADS, SMEM_BYTES>>>(x, w1, b1, b2, b3,
                                                fb1, fw2, fb2, out);
}